// round 1
// baseline (speedup 1.0000x reference)
#include <cuda_runtime.h>

// Problem constants
#define B_   64
#define L_   256
#define D_   768
#define C_   200      // LABELS
#define WLD  2304     // 3*D
#define PE_ROWS 513
#define CE_ROWS 201

// GEMM tiling
#define BM 128
#define BN 64
#define BK 16
#define TM 8
#define TN 4
// threads = (BM/TM)*(BN/TN) = 16*16 = 256

// Scratch (device globals — no allocation allowed)
__device__ float g_SW [B_ * L_ * C_];     // seq @ Wg^T   (13.1 MB)
__device__ float g_PEW[PE_ROWS * C_];     // pos_embedding @ Wp^T
__device__ float g_CEW[CE_ROWS * C_];     // class_embedding @ Wf^T

// C[m,c] = sum_k A[m,k] * W[c, w_off + k],  A: [M,768] row-major, C: [M,200]
__global__ __launch_bounds__(256) void sgemm_k768_n200(
    const float* __restrict__ A, int M,
    const float* __restrict__ W, int w_off,
    float* __restrict__ C)
{
    __shared__ float As[BK][BM];
    __shared__ float Bs[BK][BN];

    const int tid = threadIdx.x;
    const int m0 = blockIdx.x * BM;
    const int c0 = blockIdx.y * BN;
    const int ty = tid >> 4;   // 0..15 → M
    const int tx = tid & 15;   // 0..15 → N

    float acc[TM][TN];
    #pragma unroll
    for (int i = 0; i < TM; i++)
        #pragma unroll
        for (int j = 0; j < TN; j++) acc[i][j] = 0.f;

    for (int k0 = 0; k0 < D_; k0 += BK) {
        // Load A tile: BM x BK = 2048 elems, 8 per thread (k fastest → coalesced)
        #pragma unroll
        for (int i = 0; i < 8; i++) {
            int e = tid + i * 256;
            int k = e & (BK - 1);
            int m = e >> 4;
            float v = 0.f;
            if (m0 + m < M) v = A[(size_t)(m0 + m) * D_ + k0 + k];
            As[k][m] = v;
        }
        // Load B tile: BK x BN = 1024 elems, 4 per thread. B[k,c] = W[c*2304 + w_off + k]
        #pragma unroll
        for (int i = 0; i < 4; i++) {
            int e = tid + i * 256;
            int k = e & (BK - 1);
            int c = e >> 4;
            float v = 0.f;
            if (c0 + c < C_) v = W[(size_t)(c0 + c) * WLD + w_off + k0 + k];
            Bs[k][c] = v;
        }
        __syncthreads();

        #pragma unroll
        for (int kk = 0; kk < BK; kk++) {
            float a[TM], bb[TN];
            #pragma unroll
            for (int i = 0; i < TM; i++) a[i] = As[kk][ty * TM + i];
            #pragma unroll
            for (int j = 0; j < TN; j++) bb[j] = Bs[kk][tx * TN + j];
            #pragma unroll
            for (int i = 0; i < TM; i++)
                #pragma unroll
                for (int j = 0; j < TN; j++)
                    acc[i][j] = fmaf(a[i], bb[j], acc[i][j]);
        }
        __syncthreads();
    }

    #pragma unroll
    for (int i = 0; i < TM; i++) {
        int m = m0 + ty * TM + i;
        if (m >= M) continue;
        #pragma unroll
        for (int j = 0; j < TN; j++) {
            int c = c0 + tx * TN + j;
            if (c < C_) C[(size_t)m * C_ + c] = acc[i][j];
        }
    }
}

// out[b,l,c] = SW[b, hi[b,l], c] + PEW[l-pos[b]+256, c] + CEW[l==pos[b]?frame[b]:0, c] + bias[c]
__global__ __launch_bounds__(256) void epilogue_kernel(
    const int* __restrict__ head_indexes,
    const int* __restrict__ frame,
    const int* __restrict__ pos,
    const float* __restrict__ bias,
    float* __restrict__ out)
{
    const int bl = blockIdx.x;          // 0..16383
    const int b  = bl >> 8;
    const int l  = bl & 255;
    const int c  = threadIdx.x;
    if (c >= C_) return;

    const int hi  = head_indexes[bl];
    const int p   = pos[b];
    const int rel = l - p + 256;
    const int fk  = (l == p) ? frame[b] : 0;

    out[(size_t)bl * C_ + c] =
          g_SW [((size_t)b * L_ + hi) * C_ + c]
        + g_PEW[(size_t)rel * C_ + c]
        + g_CEW[(size_t)fk  * C_ + c]
        + bias[c];
}

extern "C" void kernel_launch(void* const* d_in, const int* in_sizes, int n_in,
                              void* d_out, int out_size)
{
    const float* seq   = (const float*)d_in[0];
    const float* pe    = (const float*)d_in[1];
    const float* ce    = (const float*)d_in[2];
    const float* W     = (const float*)d_in[3];
    const float* bias  = (const float*)d_in[4];
    const int*   hidx  = (const int*)  d_in[5];
    const int*   frame = (const int*)  d_in[6];
    const int*   pos   = (const int*)  d_in[7];
    float* out = (float*)d_out;

    float *dSW, *dPEW, *dCEW;
    cudaGetSymbolAddress((void**)&dSW,  g_SW);
    cudaGetSymbolAddress((void**)&dPEW, g_PEW);
    cudaGetSymbolAddress((void**)&dCEW, g_CEW);

    dim3 blk(256);
    const int nTilesN = (C_ + BN - 1) / BN;  // 4

    // Main GEMM: [16384,768] x [768,200] with W columns [0:768)
    dim3 gMain((B_ * L_ + BM - 1) / BM, nTilesN);
    sgemm_k768_n200<<<gMain, blk>>>(seq, B_ * L_, W, 0, dSW);

    // PEW: [513,768] x [768,200] with W columns [768:1536)
    dim3 gPE((PE_ROWS + BM - 1) / BM, nTilesN);
    sgemm_k768_n200<<<gPE, blk>>>(pe, PE_ROWS, W, D_, dPEW);

    // CEW: [201,768] x [768,200] with W columns [1536:2304)
    dim3 gCE((CE_ROWS + BM - 1) / BM, nTilesN);
    sgemm_k768_n200<<<gCE, blk>>>(ce, CE_ROWS, W, 2 * D_, dCEW);

    // Fused gather + add epilogue
    epilogue_kernel<<<B_ * L_, 256>>>(hidx, frame, pos, bias, out);
}

// round 2
// speedup vs baseline: 2.7989x; 2.7989x over previous
#include <cuda_runtime.h>

// Problem constants
#define B_   64
#define L_   256
#define D_   768
#define C_   200      // LABELS
#define WLD  2304     // 3*D
#define PE_ROWS 513
#define CE_ROWS 201

// GEMM tiling
#define BM 128
#define BN 128
#define BK 16
#define KT (D_ / BK)          // 48 k-iterations
#define NBLK_MAIN ((B_ * L_) / BM)              // 128
#define NBLK_PE   ((PE_ROWS + BM - 1) / BM)     // 5
#define NBLK_CE   ((CE_ROWS + BM - 1) / BM)     // 2

// Scratch (device globals — no allocation allowed)
__device__ float g_SW [B_ * L_ * C_];     // seq @ Wg^T   (13.1 MB)
__device__ float g_PEW[PE_ROWS * C_];     // pos_embedding @ Wp^T
__device__ float g_CEW[CE_ROWS * C_];     // class_embedding @ Wf^T

// Fused triple-GEMM: C[m,c] = sum_k A[m,k] * W[c, w_off + k]
// A: [M,768] row-major, C: [M,200] row-major (only c<200 stored).
// Segments: blockIdx.x in [0,128) -> seq, [128,133) -> pos_emb, [133,135) -> class_emb
__global__ __launch_bounds__(256) void sgemm_fused(
    const float* __restrict__ A0,
    const float* __restrict__ A1,
    const float* __restrict__ A2,
    const float* __restrict__ W,
    float* __restrict__ C0,
    float* __restrict__ C1,
    float* __restrict__ C2)
{
    // ---- segment select ----
    int bx = blockIdx.x;
    const float* A;
    float* C;
    int M, w_off;
    if (bx < NBLK_MAIN)              { A = A0; C = C0; M = B_ * L_;  w_off = 0;      }
    else if (bx < NBLK_MAIN+NBLK_PE) { A = A1; C = C1; M = PE_ROWS;  w_off = D_;     bx -= NBLK_MAIN; }
    else                             { A = A2; C = C2; M = CE_ROWS;  w_off = 2*D_;   bx -= NBLK_MAIN+NBLK_PE; }

    const int m0 = bx * BM;
    const int c0 = blockIdx.y * BN;
    const int tid = threadIdx.x;

    __shared__ float As[2][BK][BM];   // 16 KB
    __shared__ float Bs[2][BK][BN];   // 16 KB

    // ---- warp/thread micro-tile mapping: 8 warps as 4(M) x 2(N), warp tile 32x64 ----
    const int warpId = tid >> 5;
    const int lane   = tid & 31;
    const int warp_m = warpId & 3;        // 0..3
    const int warp_n = warpId >> 2;       // 0..1
    const int lane_m = lane >> 3;         // 0..3
    const int lane_n = lane & 7;          // 0..7
    const int m_base = warp_m * 32 + lane_m * 8;   // 0..120, mult of 8
    const int n_base = warp_n * 64 + lane_n * 8;   // 0..120, mult of 8

    // ---- global-load mapping (two float4 per thread per tile, per matrix) ----
    // tile has 512 float4; thread handles f = tid and f = tid + 256
    const int a_row0 = tid >> 2;              // f = tid
    const int a_kq0  = (tid & 3) * 4;
    const int a_row1 = (tid + 256) >> 2;      // f = tid + 256
    const int a_kq1  = a_kq0;                 // (tid+256)&3 == tid&3

    const bool a_ok0 = (m0 + a_row0) < M;
    const bool a_ok1 = (m0 + a_row1) < M;
    const bool b_ok0 = (c0 + a_row0) < C_;    // same f->index split for B (col = f>>2)
    const bool b_ok1 = (c0 + a_row1) < C_;

    const float* Arow0 = A + (size_t)(m0 + a_row0) * D_ + a_kq0;
    const float* Arow1 = A + (size_t)(m0 + a_row1) * D_ + a_kq1;
    const float* Wrow0 = W + (size_t)(c0 + a_row0) * WLD + w_off + a_kq0;
    const float* Wrow1 = W + (size_t)(c0 + a_row1) * WLD + w_off + a_kq1;

    float acc[8][8];
    #pragma unroll
    for (int i = 0; i < 8; i++)
        #pragma unroll
        for (int j = 0; j < 8; j++) acc[i][j] = 0.f;

    float4 ar0, ar1, br0, br1;
    const float4 Z4 = make_float4(0.f, 0.f, 0.f, 0.f);

    // prologue: load tile 0
    ar0 = a_ok0 ? *(const float4*)(Arow0) : Z4;
    ar1 = a_ok1 ? *(const float4*)(Arow1) : Z4;
    br0 = b_ok0 ? *(const float4*)(Wrow0) : Z4;
    br1 = b_ok1 ? *(const float4*)(Wrow1) : Z4;

    int buf = 0;
    {
        As[buf][a_kq0+0][a_row0] = ar0.x; As[buf][a_kq0+1][a_row0] = ar0.y;
        As[buf][a_kq0+2][a_row0] = ar0.z; As[buf][a_kq0+3][a_row0] = ar0.w;
        As[buf][a_kq1+0][a_row1] = ar1.x; As[buf][a_kq1+1][a_row1] = ar1.y;
        As[buf][a_kq1+2][a_row1] = ar1.z; As[buf][a_kq1+3][a_row1] = ar1.w;
        Bs[buf][a_kq0+0][a_row0] = br0.x; Bs[buf][a_kq0+1][a_row0] = br0.y;
        Bs[buf][a_kq0+2][a_row0] = br0.z; Bs[buf][a_kq0+3][a_row0] = br0.w;
        Bs[buf][a_kq1+0][a_row1] = br1.x; Bs[buf][a_kq1+1][a_row1] = br1.y;
        Bs[buf][a_kq1+2][a_row1] = br1.z; Bs[buf][a_kq1+3][a_row1] = br1.w;
    }
    __syncthreads();

    for (int kt = 0; kt < KT; kt++) {
        const bool more = (kt + 1) < KT;
        if (more) {
            const int ko = (kt + 1) * BK;
            ar0 = a_ok0 ? *(const float4*)(Arow0 + ko) : Z4;
            ar1 = a_ok1 ? *(const float4*)(Arow1 + ko) : Z4;
            br0 = b_ok0 ? *(const float4*)(Wrow0 + ko) : Z4;
            br1 = b_ok1 ? *(const float4*)(Wrow1 + ko) : Z4;
        }

        #pragma unroll
        for (int kk = 0; kk < BK; kk++) {
            float4 aA = *(const float4*)&As[buf][kk][m_base];
            float4 aB = *(const float4*)&As[buf][kk][m_base + 4];
            float4 bA = *(const float4*)&Bs[buf][kk][n_base];
            float4 bB = *(const float4*)&Bs[buf][kk][n_base + 4];
            float a[8] = {aA.x, aA.y, aA.z, aA.w, aB.x, aB.y, aB.z, aB.w};
            float bb[8] = {bA.x, bA.y, bA.z, bA.w, bB.x, bB.y, bB.z, bB.w};
            #pragma unroll
            for (int i = 0; i < 8; i++)
                #pragma unroll
                for (int j = 0; j < 8; j++)
                    acc[i][j] = fmaf(a[i], bb[j], acc[i][j]);
        }

        if (more) {
            const int nb = buf ^ 1;
            As[nb][a_kq0+0][a_row0] = ar0.x; As[nb][a_kq0+1][a_row0] = ar0.y;
            As[nb][a_kq0+2][a_row0] = ar0.z; As[nb][a_kq0+3][a_row0] = ar0.w;
            As[nb][a_kq1+0][a_row1] = ar1.x; As[nb][a_kq1+1][a_row1] = ar1.y;
            As[nb][a_kq1+2][a_row1] = ar1.z; As[nb][a_kq1+3][a_row1] = ar1.w;
            Bs[nb][a_kq0+0][a_row0] = br0.x; Bs[nb][a_kq0+1][a_row0] = br0.y;
            Bs[nb][a_kq0+2][a_row0] = br0.z; Bs[nb][a_kq0+3][a_row0] = br0.w;
            Bs[nb][a_kq1+0][a_row1] = br1.x; Bs[nb][a_kq1+1][a_row1] = br1.y;
            Bs[nb][a_kq1+2][a_row1] = br1.z; Bs[nb][a_kq1+3][a_row1] = br1.w;
            __syncthreads();
            buf = nb;
        }
    }

    // ---- epilogue: float4 stores, predicated on bounds ----
    #pragma unroll
    for (int i = 0; i < 8; i++) {
        const int m = m0 + m_base + i;
        if (m >= M) continue;
        float* Crow = C + (size_t)m * C_;
        #pragma unroll
        for (int jq = 0; jq < 2; jq++) {
            const int c = c0 + n_base + jq * 4;
            if (c < C_) {   // c mult of 4, C_=200 mult of 4 -> full float4 in-bounds
                float4 v = make_float4(acc[i][jq*4+0], acc[i][jq*4+1],
                                       acc[i][jq*4+2], acc[i][jq*4+3]);
                *(float4*)(Crow + c) = v;
            }
        }
    }
}

// out[b,l,:] = SW[b, hi[b,l], :] + PEW[l-pos[b]+256, :] + CEW[l==pos[b]?frame[b]:0, :] + bias
// 200 floats = 50 float4 per row; 4 rows per 256-thread block (64 lanes/row, 50 active)
__global__ __launch_bounds__(256) void epilogue_kernel(
    const int* __restrict__ head_indexes,
    const int* __restrict__ frame,
    const int* __restrict__ pos,
    const float* __restrict__ bias,
    float* __restrict__ out)
{
    const int t = threadIdx.x;
    const int r = (blockIdx.x << 2) + (t >> 6);   // global (b,l) row
    const int lane = t & 63;
    if (lane >= C_ / 4) return;                    // 50 float4 per row

    const int b = r >> 8;
    const int l = r & 255;

    const int hi  = __ldg(&head_indexes[r]);
    const int p   = __ldg(&pos[b]);
    const int rel = l - p + 256;
    const int fk  = (l == p) ? __ldg(&frame[b]) : 0;

    const float4* sw = (const float4*)(g_SW  + ((size_t)b * L_ + hi) * C_);
    const float4* pw = (const float4*)(g_PEW + (size_t)rel * C_);
    const float4* cw = (const float4*)(g_CEW + (size_t)fk  * C_);
    const float4* bi = (const float4*)bias;

    float4 s = sw[lane], q = pw[lane], f = cw[lane], z = bi[lane];
    float4 o;
    o.x = s.x + q.x + f.x + z.x;
    o.y = s.y + q.y + f.y + z.y;
    o.z = s.z + q.z + f.z + z.z;
    o.w = s.w + q.w + f.w + z.w;
    ((float4*)(out + (size_t)r * C_))[lane] = o;
}

extern "C" void kernel_launch(void* const* d_in, const int* in_sizes, int n_in,
                              void* d_out, int out_size)
{
    const float* seq   = (const float*)d_in[0];
    const float* pe    = (const float*)d_in[1];
    const float* ce    = (const float*)d_in[2];
    const float* W     = (const float*)d_in[3];
    const float* bias  = (const float*)d_in[4];
    const int*   hidx  = (const int*)  d_in[5];
    const int*   frame = (const int*)  d_in[6];
    const int*   pos   = (const int*)  d_in[7];
    float* out = (float*)d_out;

    float *dSW, *dPEW, *dCEW;
    cudaGetSymbolAddress((void**)&dSW,  g_SW);
    cudaGetSymbolAddress((void**)&dPEW, g_PEW);
    cudaGetSymbolAddress((void**)&dCEW, g_CEW);

    // Fused triple GEMM (seq/pos_emb/class_emb share the launch)
    dim3 gG(NBLK_MAIN + NBLK_PE + NBLK_CE, (C_ + BN - 1) / BN);  // (135, 2)
    sgemm_fused<<<gG, 256>>>(seq, pe, ce, W, dSW, dPEW, dCEW);

    // Fused gather + add epilogue (4 rows per block)
    epilogue_kernel<<<(B_ * L_) / 4, 256>>>(hidx, frame, pos, bias, out);
}

// round 3
// speedup vs baseline: 6.8233x; 2.4379x over previous
#include <cuda_runtime.h>
#include <cuda_bf16.h>
#include <cstdint>

// Problem constants
#define B_   64
#define L_   256
#define D_   768
#define C_   200      // LABELS
#define WLD  2304     // 3*D
#define PE_ROWS 513
#define CE_ROWS 201

// GEMM tiling
#define BM 128
#define BN 128
#define BK 32
#define KT (D_ / BK)          // 24 k-iterations
#define P_ 40                 // smem pitch in bf16 elems (80 bytes -> conflict-free frags)
#define NBLK_MAIN ((B_ * L_) / BM)              // 128
#define NBLK_PE   ((PE_ROWS + BM - 1) / BM)     // 5
#define NBLK_CE   ((CE_ROWS + BM - 1) / BM)     // 2

// smem: per buffer 4 tiles (Ahi, Alo, Bhi, Blo) each 128*P_ bf16 = 10240 B
#define TILE_B   (128 * P_ * 2)                 // 10240
#define BUF_B    (4 * TILE_B)                   // 40960
#define SMEM_TOT (2 * BUF_B)                    // 81920

// Scratch (device globals — no allocation allowed)
__device__ float g_SW [B_ * L_ * C_];     // seq @ Wg^T   (13.1 MB)
__device__ float g_PEW[PE_ROWS * C_];     // pos_embedding @ Wp^T
__device__ float g_CEW[CE_ROWS * C_];     // class_embedding @ Wf^T

__device__ __forceinline__ void mma16816(float* d, const uint32_t* a, const uint32_t* b) {
    asm volatile(
        "mma.sync.aligned.m16n8k16.row.col.f32.bf16.bf16.f32 "
        "{%0,%1,%2,%3}, {%4,%5,%6,%7}, {%8,%9}, {%0,%1,%2,%3};\n"
        : "+f"(d[0]), "+f"(d[1]), "+f"(d[2]), "+f"(d[3])
        : "r"(a[0]), "r"(a[1]), "r"(a[2]), "r"(a[3]), "r"(b[0]), "r"(b[1]));
}

// split x,y into bf16 hi (returned packed) and fp32 residuals
__device__ __forceinline__ uint32_t hi_pack2(float x, float y, float& rx, float& ry) {
    __nv_bfloat162 h = __floats2bfloat162_rn(x, y);
    rx = x - __bfloat162float(h.x);
    ry = y - __bfloat162float(h.y);
    return *reinterpret_cast<uint32_t*>(&h);
}
__device__ __forceinline__ uint32_t lo_pack2(float x, float y) {
    __nv_bfloat162 h = __floats2bfloat162_rn(x, y);
    return *reinterpret_cast<uint32_t*>(&h);
}

// convert float4 -> hi/lo bf16x4 and store to smem tiles at (row, kq)
__device__ __forceinline__ void stage4(char* hiT, char* loT, int row, int kq, float4 v) {
    float rx, ry, rz, rw;
    uint32_t h01 = hi_pack2(v.x, v.y, rx, ry);
    uint32_t h23 = hi_pack2(v.z, v.w, rz, rw);
    uint32_t l01 = lo_pack2(rx, ry);
    uint32_t l23 = lo_pack2(rz, rw);
    size_t off = ((size_t)row * P_ + kq) * 2;
    *reinterpret_cast<uint2*>(hiT + off) = make_uint2(h01, h23);
    *reinterpret_cast<uint2*>(loT + off) = make_uint2(l01, l23);
}

// Fused triple-GEMM: C[m,c] = sum_k A[m,k] * W[c, w_off + k]
// bf16-split 3-product tensor-core GEMM (error ~1e-5, far under 1e-3 gate)
__global__ __launch_bounds__(256) void bfgemm_fused(
    const float* __restrict__ A0,
    const float* __restrict__ A1,
    const float* __restrict__ A2,
    const float* __restrict__ W,
    float* __restrict__ C0,
    float* __restrict__ C1,
    float* __restrict__ C2)
{
    // ---- segment select ----
    int bx = blockIdx.x;
    const float* A;
    float* C;
    int M, w_off;
    if (bx < NBLK_MAIN)                { A = A0; C = C0; M = B_ * L_;  w_off = 0;    }
    else if (bx < NBLK_MAIN + NBLK_PE) { A = A1; C = C1; M = PE_ROWS;  w_off = D_;   bx -= NBLK_MAIN; }
    else                               { A = A2; C = C2; M = CE_ROWS;  w_off = 2*D_; bx -= NBLK_MAIN + NBLK_PE; }

    const int m0 = bx * BM;
    const int c0 = blockIdx.y * BN;
    const int tid = threadIdx.x;
    const int lane = tid & 31;
    const int warpId = tid >> 5;
    const int g   = lane >> 2;     // 0..7
    const int tig = lane & 3;      // 0..3

    const int warp_m = warpId & 1;   // 2 M-warps, 64 rows each
    const int warp_n = warpId >> 1;  // 4 N-warps, 32 cols each

    extern __shared__ __align__(16) char smem[];
    // per-buffer layout: [Ahi | Alo | Bhi | Blo], each TILE_B bytes

    // ---- global-load mapping: 1024 float4 per tile per matrix, 4 per thread ----
    const int ld_row = tid >> 3;           // base row, +32 per i
    const int ld_kq  = (tid & 7) * 4;      // k offset within BK

    bool a_ok[4], b_ok[4];
    const float* Ap[4];
    const float* Wp[4];
    #pragma unroll
    for (int i = 0; i < 4; i++) {
        int r = ld_row + i * 32;
        a_ok[i] = (m0 + r) < M;
        b_ok[i] = (c0 + r) < C_;
        Ap[i] = A + (size_t)(m0 + r) * D_ + ld_kq;
        Wp[i] = W + (size_t)(c0 + r) * WLD + w_off + ld_kq;
    }

    float acc[4][4][4];
    #pragma unroll
    for (int mt = 0; mt < 4; mt++)
        #pragma unroll
        for (int nt = 0; nt < 4; nt++)
            #pragma unroll
            for (int r = 0; r < 4; r++) acc[mt][nt][r] = 0.f;

    const float4 Z4 = make_float4(0.f, 0.f, 0.f, 0.f);
    float4 av[4], bv[4];

    // prologue: load tile 0
    #pragma unroll
    for (int i = 0; i < 4; i++) {
        av[i] = a_ok[i] ? *(const float4*)(Ap[i]) : Z4;
        bv[i] = b_ok[i] ? *(const float4*)(Wp[i]) : Z4;
    }
    int buf = 0;
    {
        char* ah = smem;              char* al = smem + TILE_B;
        char* bh = smem + 2*TILE_B;   char* bl = smem + 3*TILE_B;
        #pragma unroll
        for (int i = 0; i < 4; i++) {
            stage4(ah, al, ld_row + i*32, ld_kq, av[i]);
            stage4(bh, bl, ld_row + i*32, ld_kq, bv[i]);
        }
    }
    __syncthreads();

    for (int kt = 0; kt < KT; kt++) {
        const bool more = (kt + 1) < KT;
        if (more) {
            const int ko = (kt + 1) * BK;
            #pragma unroll
            for (int i = 0; i < 4; i++) {
                av[i] = a_ok[i] ? *(const float4*)(Ap[i] + ko) : Z4;
                bv[i] = b_ok[i] ? *(const float4*)(Wp[i] + ko) : Z4;
            }
        }

        char* ahT = smem + buf*BUF_B;
        char* alT = ahT + TILE_B;
        char* bhT = ahT + 2*TILE_B;
        char* blT = ahT + 3*TILE_B;

        #pragma unroll
        for (int ks = 0; ks < 2; ks++) {
            const int kb = ks * 16 + 2 * tig;

            // B fragments for all 4 n-tiles (hi & lo)
            uint32_t b_hi[4][2], b_lo[4][2];
            #pragma unroll
            for (int nt = 0; nt < 4; nt++) {
                const int n_local = warp_n * 32 + nt * 8 + g;
                size_t o0 = ((size_t)n_local * P_ + kb) * 2;
                size_t o1 = ((size_t)n_local * P_ + kb + 8) * 2;
                b_hi[nt][0] = *(const uint32_t*)(bhT + o0);
                b_hi[nt][1] = *(const uint32_t*)(bhT + o1);
                b_lo[nt][0] = *(const uint32_t*)(blT + o0);
                b_lo[nt][1] = *(const uint32_t*)(blT + o1);
            }

            #pragma unroll
            for (int mt = 0; mt < 4; mt++) {
                const int mbase = warp_m * 64 + mt * 16;
                size_t o00 = ((size_t)(mbase + g)     * P_ + kb) * 2;
                size_t o10 = ((size_t)(mbase + 8 + g) * P_ + kb) * 2;
                uint32_t a_hi[4], a_lo[4];
                a_hi[0] = *(const uint32_t*)(ahT + o00);
                a_hi[1] = *(const uint32_t*)(ahT + o10);
                a_hi[2] = *(const uint32_t*)(ahT + o00 + 16);   // k+8 -> +16 bytes
                a_hi[3] = *(const uint32_t*)(ahT + o10 + 16);
                a_lo[0] = *(const uint32_t*)(alT + o00);
                a_lo[1] = *(const uint32_t*)(alT + o10);
                a_lo[2] = *(const uint32_t*)(alT + o00 + 16);
                a_lo[3] = *(const uint32_t*)(alT + o10 + 16);

                #pragma unroll
                for (int nt = 0; nt < 4; nt++) {
                    mma16816(acc[mt][nt], a_hi, b_hi[nt]);   // Ah*Bh
                    mma16816(acc[mt][nt], a_hi, b_lo[nt]);   // Ah*Bl
                    mma16816(acc[mt][nt], a_lo, b_hi[nt]);   // Al*Bh
                }
            }
        }

        if (more) {
            const int nb = buf ^ 1;
            char* ah = smem + nb*BUF_B;   char* al = ah + TILE_B;
            char* bh = ah + 2*TILE_B;     char* bl = ah + 3*TILE_B;
            #pragma unroll
            for (int i = 0; i < 4; i++) {
                stage4(ah, al, ld_row + i*32, ld_kq, av[i]);
                stage4(bh, bl, ld_row + i*32, ld_kq, bv[i]);
            }
            __syncthreads();
            buf = nb;
        }
    }

    // ---- store: float2 per (mt,nt) half, predicated ----
    #pragma unroll
    for (int mt = 0; mt < 4; mt++) {
        const int m_g = m0 + warp_m * 64 + mt * 16 + g;
        #pragma unroll
        for (int nt = 0; nt < 4; nt++) {
            const int n_g = c0 + warp_n * 32 + nt * 8 + 2 * tig;
            if (n_g < C_) {
                if (m_g < M)
                    *(float2*)(C + (size_t)m_g * C_ + n_g) =
                        make_float2(acc[mt][nt][0], acc[mt][nt][1]);
                if (m_g + 8 < M)
                    *(float2*)(C + (size_t)(m_g + 8) * C_ + n_g) =
                        make_float2(acc[mt][nt][2], acc[mt][nt][3]);
            }
        }
    }
}

// out[b,l,:] = SW[b, hi[b,l], :] + PEW[l-pos[b]+256, :] + CEW[l==pos[b]?frame[b]:0, :] + bias
__global__ __launch_bounds__(256) void epilogue_kernel(
    const int* __restrict__ head_indexes,
    const int* __restrict__ frame,
    const int* __restrict__ pos,
    const float* __restrict__ bias,
    float* __restrict__ out)
{
    const int t = threadIdx.x;
    const int r = (blockIdx.x << 2) + (t >> 6);   // global (b,l) row
    const int lane = t & 63;
    if (lane >= C_ / 4) return;                    // 50 float4 per row

    const int b = r >> 8;
    const int l = r & 255;

    const int hi  = __ldg(&head_indexes[r]);
    const int p   = __ldg(&pos[b]);
    const int rel = l - p + 256;
    const int fk  = (l == p) ? __ldg(&frame[b]) : 0;

    const float4* sw = (const float4*)(g_SW  + ((size_t)b * L_ + hi) * C_);
    const float4* pw = (const float4*)(g_PEW + (size_t)rel * C_);
    const float4* cw = (const float4*)(g_CEW + (size_t)fk  * C_);
    const float4* bi = (const float4*)bias;

    float4 s = sw[lane], q = pw[lane], f = cw[lane], z = bi[lane];
    float4 o;
    o.x = s.x + q.x + f.x + z.x;
    o.y = s.y + q.y + f.y + z.y;
    o.z = s.z + q.z + f.z + z.z;
    o.w = s.w + q.w + f.w + z.w;
    ((float4*)(out + (size_t)r * C_))[lane] = o;
}

extern "C" void kernel_launch(void* const* d_in, const int* in_sizes, int n_in,
                              void* d_out, int out_size)
{
    const float* seq   = (const float*)d_in[0];
    const float* pe    = (const float*)d_in[1];
    const float* ce    = (const float*)d_in[2];
    const float* W     = (const float*)d_in[3];
    const float* bias  = (const float*)d_in[4];
    const int*   hidx  = (const int*)  d_in[5];
    const int*   frame = (const int*)  d_in[6];
    const int*   pos   = (const int*)  d_in[7];
    float* out = (float*)d_out;

    float *dSW, *dPEW, *dCEW;
    cudaGetSymbolAddress((void**)&dSW,  g_SW);
    cudaGetSymbolAddress((void**)&dPEW, g_PEW);
    cudaGetSymbolAddress((void**)&dCEW, g_CEW);

    static int smem_set = 0;
    if (!smem_set) {
        cudaFuncSetAttribute(bfgemm_fused,
                             cudaFuncAttributeMaxDynamicSharedMemorySize, SMEM_TOT);
        smem_set = 1;
    }

    // Fused triple GEMM (seq/pos_emb/class_emb share the launch)
    dim3 gG(NBLK_MAIN + NBLK_PE + NBLK_CE, (C_ + BN - 1) / BN);  // (135, 2)
    bfgemm_fused<<<gG, 256, SMEM_TOT>>>(seq, pe, ce, W, dSW, dPEW, dCEW);

    // Fused gather + add epilogue (4 rows per block)
    epilogue_kernel<<<(B_ * L_) / 4, 256>>>(hidx, frame, pos, bias, out);
}

// round 5
// speedup vs baseline: 7.2007x; 1.0553x over previous
#include <cuda_runtime.h>
#include <cuda_bf16.h>
#include <cstdint>

// Problem constants
#define B_   64
#define L_   256
#define D_   768
#define C_   200
#define WLD  2304
#define PE_ROWS 513
#define CE_ROWS 201

// GEMM tiling
#define BM 128
#define BN 128
#define BK 32
#define KT 24                 // 768/32
#define P_ 40                 // smem pitch in bf16 (80B rows: conflict-free LDS/ldmatrix)
#define NBLK_MAIN 128
#define NBLK_PE   5
#define NBLK_CE   2

#define TILE_HALF 10240       // 128 rows * 40 * 2B
#define TILE_PAIR 20480       // hi + lo
#define SM_B_BASE 40960       // A double buffer occupies [0, 40960)
#define SMEM_TOT  81920

// Scratch (device globals — no allocation allowed)
__device__ float g_SW [B_ * L_ * C_];
__device__ float g_PEW[PE_ROWS * C_];
__device__ float g_CEW[CE_ROWS * C_];
// W prepacked as smem tile images: [seg(3)][cblk(2)][kt(24)] x (hi|lo) pitch-40 bf16
__device__ __align__(16) char g_Wimg[3 * 2 * KT * TILE_PAIR];   // ~2.95 MB

// ---------------- helpers ----------------
__device__ __forceinline__ uint32_t smem_u32(const void* p) {
    uint32_t a;
    asm("{ .reg .u64 t; cvta.to.shared.u64 t, %1; cvt.u32.u64 %0, t; }" : "=r"(a) : "l"(p));
    return a;
}
__device__ __forceinline__ void mma16816(float* d, const uint32_t* a, const uint32_t* b) {
    asm volatile(
        "mma.sync.aligned.m16n8k16.row.col.f32.bf16.bf16.f32 "
        "{%0,%1,%2,%3}, {%4,%5,%6,%7}, {%8,%9}, {%0,%1,%2,%3};\n"
        : "+f"(d[0]), "+f"(d[1]), "+f"(d[2]), "+f"(d[3])
        : "r"(a[0]), "r"(a[1]), "r"(a[2]), "r"(a[3]), "r"(b[0]), "r"(b[1]));
}
__device__ __forceinline__ void ldmx4(uint32_t& r0, uint32_t& r1, uint32_t& r2, uint32_t& r3,
                                      uint32_t addr) {
    asm volatile("ldmatrix.sync.aligned.m8n8.x4.shared.b16 {%0,%1,%2,%3}, [%4];"
                 : "=r"(r0), "=r"(r1), "=r"(r2), "=r"(r3) : "r"(addr));
}
#define CP_ASYNC16(dst, src) \
    asm volatile("cp.async.cg.shared.global [%0], [%1], 16;" :: "r"(dst), "l"(src))
#define CP_COMMIT()  asm volatile("cp.async.commit_group;" ::: "memory")
#define CP_WAIT0()   asm volatile("cp.async.wait_group 0;" ::: "memory")

__device__ __forceinline__ uint32_t hi_pack2(float x, float y, float& rx, float& ry) {
    __nv_bfloat162 h = __floats2bfloat162_rn(x, y);
    rx = x - __bfloat162float(h.x);
    ry = y - __bfloat162float(h.y);
    return *reinterpret_cast<uint32_t*>(&h);
}
__device__ __forceinline__ uint32_t lo_pack2(float x, float y) {
    __nv_bfloat162 h = __floats2bfloat162_rn(x, y);
    return *reinterpret_cast<uint32_t*>(&h);
}

// ---------------- prepack W -> bf16 hi/lo smem-image tiles ----------------
__global__ __launch_bounds__(256) void prepack_W(const float* __restrict__ W) {
    const int idx   = blockIdx.x * 256 + threadIdx.x;   // 144 images * 1024 = 147456
    const int image = idx >> 10;
    const int rem   = idx & 1023;
    const int row   = rem >> 3;         // 0..127 (class within cblk, padded)
    const int c4    = rem & 7;          // float4 within 32-col k chunk

    const int seg  = image / (2 * KT);
    const int rem2 = image % (2 * KT);
    const int cblk = rem2 / KT;
    const int kt   = rem2 % KT;

    const int cls = cblk * 128 + row;
    float4 v = make_float4(0.f, 0.f, 0.f, 0.f);
    if (cls < C_)
        v = *(const float4*)(W + (size_t)cls * WLD + seg * D_ + kt * BK + c4 * 4);

    float rx, ry, rz, rw;
    uint32_t h01 = hi_pack2(v.x, v.y, rx, ry);
    uint32_t h23 = hi_pack2(v.z, v.w, rz, rw);
    uint32_t l01 = lo_pack2(rx, ry);
    uint32_t l23 = lo_pack2(rz, rw);

    char* img = g_Wimg + (size_t)image * TILE_PAIR;
    const uint32_t off = (uint32_t)row * 80 + c4 * 8;   // (row*P_ + c4*4)*2 bytes
    *(uint2*)(img + off)             = make_uint2(h01, h23);
    *(uint2*)(img + TILE_HALF + off) = make_uint2(l01, l23);
    if (c4 == 7) {   // zero pitch padding (cols 32..39)
        const uint32_t po = (uint32_t)row * 80 + 64;
        *(uint4*)(img + po)             = make_uint4(0, 0, 0, 0);
        *(uint4*)(img + TILE_HALF + po) = make_uint4(0, 0, 0, 0);
    }
}

// ---------------- fused triple GEMM (mma.sync + ldmatrix + cp.async) ----------------
__global__ __launch_bounds__(256) void bfgemm_fused(
    const float* __restrict__ A0,
    const float* __restrict__ A1,
    const float* __restrict__ A2,
    const float* __restrict__ bias,
    float* __restrict__ C0,
    float* __restrict__ C1,
    float* __restrict__ C2)
{
    // segment select
    int bx = blockIdx.x;
    const float* A;
    float* C;
    int M, seg;
    if (bx < NBLK_MAIN)                { A = A0; C = C0; M = B_ * L_; seg = 0; }
    else if (bx < NBLK_MAIN + NBLK_PE) { A = A1; C = C1; M = PE_ROWS; seg = 1; bx -= NBLK_MAIN; }
    else                               { A = A2; C = C2; M = CE_ROWS; seg = 2; bx -= NBLK_MAIN + NBLK_PE; }
    const int m0   = bx * BM;
    const int cblk = blockIdx.y;
    const int c0   = cblk * BN;

    extern __shared__ __align__(16) char smem[];
    const uint32_t sb = smem_u32(smem);

    const int tid  = threadIdx.x;
    const int lane = tid & 31;
    const int wid  = tid >> 5;
    const int warp_m = wid & 1;    // 2 M-warps (64 rows each)
    const int warp_n = wid >> 1;   // 4 N-warps (32 cols each)

    // ldmatrix lane geometry
    const int am = (lane & 7) + ((lane >> 3) & 1) * 8;   // A row within 16
    const int ak = (lane >> 4) * 8;                      // A k offset
    const int bn = (lane & 7) + (lane >> 4) * 8;         // B row within 16 (nt pair)
    const int bk = ((lane >> 3) & 1) * 8;                // B k offset

    // A staging geometry: 4 float4/thread
    const int st_row = tid >> 3;   // +32 per i
    const int st_c4  = tid & 7;

    const char* wimg = g_Wimg + (size_t)((seg * 2 + cblk) * KT) * TILE_PAIR;

    float acc[4][4][4];
    #pragma unroll
    for (int mt = 0; mt < 4; mt++)
        #pragma unroll
        for (int nt = 0; nt < 4; nt++)
            #pragma unroll
            for (int r = 0; r < 4; r++) acc[mt][nt][r] = 0.f;

    // ---- staging helpers ----
    auto stageB = [&](int kt, int b) {
        const uint32_t dst = sb + SM_B_BASE + b * TILE_PAIR;
        const char* src = wimg + (size_t)kt * TILE_PAIR;
        #pragma unroll
        for (int i = 0; i < 5; i++) {
            const uint32_t o = (uint32_t)(tid + i * 256) * 16;
            CP_ASYNC16(dst + o, src + o);
        }
        CP_COMMIT();
    };
    auto stageA = [&](int kt, int b) {
        char* dst = smem + b * TILE_PAIR;
        #pragma unroll
        for (int i = 0; i < 4; i++) {
            const int row = st_row + i * 32;
            float4 v = make_float4(0.f, 0.f, 0.f, 0.f);
            if (m0 + row < M)
                v = *(const float4*)(A + (size_t)(m0 + row) * D_ + kt * BK + st_c4 * 4);
            float rx, ry, rz, rw;
            uint32_t h01 = hi_pack2(v.x, v.y, rx, ry);
            uint32_t h23 = hi_pack2(v.z, v.w, rz, rw);
            const uint32_t off = (uint32_t)row * 80 + st_c4 * 8;
            *(uint2*)(dst + off)             = make_uint2(h01, h23);
            *(uint2*)(dst + TILE_HALF + off) = make_uint2(lo_pack2(rx, ry), lo_pack2(rz, rw));
        }
    };

    // prologue: stage kt=0 into buffer 0
    stageB(0, 0);
    stageA(0, 0);
    CP_WAIT0();
    __syncthreads();

    #pragma unroll 1
    for (int kt = 0; kt < KT; kt++) {
        const int b = kt & 1;
        if (kt + 1 < KT) {           // prefetch next tile into other buffer
            stageB(kt + 1, b ^ 1);
            stageA(kt + 1, b ^ 1);
        }

        const uint32_t Ab = sb + b * TILE_PAIR;
        const uint32_t Bb = sb + SM_B_BASE + b * TILE_PAIR;

        #pragma unroll
        for (int ks = 0; ks < 2; ks++) {
            // B fragments: 2 ldmatrix.x4 per half cover 4 nt tiles
            uint32_t bh[4][2], bl[4][2];
            #pragma unroll
            for (int p = 0; p < 2; p++) {
                const uint32_t ba = Bb +
                    ((uint32_t)(warp_n * 32 + p * 16 + bn) * P_ + ks * 16 + bk) * 2;
                ldmx4(bh[2*p][0], bh[2*p][1], bh[2*p+1][0], bh[2*p+1][1], ba);
                ldmx4(bl[2*p][0], bl[2*p][1], bl[2*p+1][0], bl[2*p+1][1], ba + TILE_HALF);
            }
            #pragma unroll
            for (int mt = 0; mt < 4; mt++) {
                const uint32_t aa = Ab +
                    ((uint32_t)(warp_m * 64 + mt * 16 + am) * P_ + ks * 16 + ak) * 2;
                uint32_t a_h[4], a_l[4];
                ldmx4(a_h[0], a_h[1], a_h[2], a_h[3], aa);
                ldmx4(a_l[0], a_l[1], a_l[2], a_l[3], aa + TILE_HALF);
                #pragma unroll
                for (int nt = 0; nt < 4; nt++) {
                    mma16816(acc[mt][nt], a_h, bh[nt]);   // Ah*Bh
                    mma16816(acc[mt][nt], a_h, bl[nt]);   // Ah*Bl
                    mma16816(acc[mt][nt], a_l, bh[nt]);   // Al*Bh
                }
            }
        }

        if (kt + 1 < KT) {
            CP_WAIT0();
            __syncthreads();
        }
    }

    // ---- store (bias folded into CEW segment) ----
    const int g   = lane >> 2;
    const int tig = lane & 3;
    #pragma unroll
    for (int mt = 0; mt < 4; mt++) {
        const int m_g = m0 + warp_m * 64 + mt * 16 + g;
        #pragma unroll
        for (int nt = 0; nt < 4; nt++) {
            const int n_g = c0 + warp_n * 32 + nt * 8 + 2 * tig;
            if (n_g < C_) {
                float b0 = 0.f, b1 = 0.f;
                if (seg == 2) { b0 = bias[n_g]; b1 = bias[n_g + 1]; }
                if (m_g < M)
                    *(float2*)(C + (size_t)m_g * C_ + n_g) =
                        make_float2(acc[mt][nt][0] + b0, acc[mt][nt][1] + b1);
                if (m_g + 8 < M)
                    *(float2*)(C + (size_t)(m_g + 8) * C_ + n_g) =
                        make_float2(acc[mt][nt][2] + b0, acc[mt][nt][3] + b1);
            }
        }
    }
}

// ---------------- gather + add epilogue (bias already in CEW) ----------------
__global__ __launch_bounds__(256) void epilogue_kernel(
    const int* __restrict__ head_indexes,
    const int* __restrict__ frame,
    const int* __restrict__ pos,
    float* __restrict__ out)
{
    const int t = threadIdx.x;
    const int r = (blockIdx.x << 2) + (t >> 6);
    const int lane = t & 63;
    if (lane >= C_ / 4) return;

    const int b = r >> 8;
    const int l = r & 255;

    const int hi  = __ldg(&head_indexes[r]);
    const int p   = __ldg(&pos[b]);
    const int rel = l - p + 256;
    const int fk  = (l == p) ? __ldg(&frame[b]) : 0;

    const float4* sw = (const float4*)(g_SW  + ((size_t)b * L_ + hi) * C_);
    const float4* pw = (const float4*)(g_PEW + (size_t)rel * C_);
    const float4* cw = (const float4*)(g_CEW + (size_t)fk  * C_);

    float4 s = sw[lane], q = pw[lane], f = cw[lane];
    float4 o;
    o.x = s.x + q.x + f.x;
    o.y = s.y + q.y + f.y;
    o.z = s.z + q.z + f.z;
    o.w = s.w + q.w + f.w;
    ((float4*)(out + (size_t)r * C_))[lane] = o;
}

extern "C" void kernel_launch(void* const* d_in, const int* in_sizes, int n_in,
                              void* d_out, int out_size)
{
    const float* seq   = (const float*)d_in[0];
    const float* pe    = (const float*)d_in[1];
    const float* ce    = (const float*)d_in[2];
    const float* W     = (const float*)d_in[3];
    const float* bias  = (const float*)d_in[4];
    const int*   hidx  = (const int*)  d_in[5];
    const int*   frame = (const int*)  d_in[6];
    const int*   pos   = (const int*)  d_in[7];
    float* out = (float*)d_out;

    float *dSW, *dPEW, *dCEW;
    cudaGetSymbolAddress((void**)&dSW,  g_SW);
    cudaGetSymbolAddress((void**)&dPEW, g_PEW);
    cudaGetSymbolAddress((void**)&dCEW, g_CEW);

    static int init_done = 0;
    if (!init_done) {
        cudaFuncSetAttribute(bfgemm_fused,
                             cudaFuncAttributeMaxDynamicSharedMemorySize, SMEM_TOT);
        init_done = 1;
    }

    // 1) prepack W -> bf16 hi/lo smem tile images
    prepack_W<<<576, 256>>>(W);

    // 2) fused triple GEMM
    dim3 gG(NBLK_MAIN + NBLK_PE + NBLK_CE, 2);   // (135, 2)
    bfgemm_fused<<<gG, 256, SMEM_TOT>>>(seq, pe, ce, bias, dSW, dPEW, dCEW);

    // 3) gather + add epilogue
    epilogue_kernel<<<(B_ * L_) / 4, 256>>>(hidx, frame, pos, out);
}

// round 6
// speedup vs baseline: 9.3372x; 1.2967x over previous
#include <cuda_runtime.h>
#include <cuda_bf16.h>
#include <cstdint>

// Problem constants
#define B_   64
#define L_   256
#define D_   768
#define C_   200
#define WLD  2304
#define PE_ROWS 513
#define CE_ROWS 201

// GEMM tiling
#define BM 128
#define BN 128
#define BK 32
#define KT 24                  // 768/32
#define P32 36                 // smem row pitch in 32-bit words (144 B)
#define NBLK_MAIN 128
#define NBLK_PE   5
#define NBLK_CE   2

// smem word offsets (tile = 128 rows * 36 words = 4608 words = 18432 B)
#define AW0 0
#define BW0 4608
#define AW1 9216
#define BW1 13824
#define SMEM_TOT 73728

// Scratch (device globals — no allocation allowed)
__device__ float g_SW [B_ * L_ * C_];
__device__ float g_PEW[PE_ROWS * C_];
__device__ float g_CEW[CE_ROWS * C_];
// W prepacked as tf32 smem tile images: [seg(3)][cblk(2)][kt(24)], 128 x P32 words
__device__ __align__(16) uint32_t g_Wimg32[3 * 2 * KT * 128 * P32];   // ~2.65 MB

// ---------------- helpers ----------------
__device__ __forceinline__ uint32_t smem_u32(const void* p) {
    uint32_t a;
    asm("{ .reg .u64 t; cvta.to.shared.u64 t, %1; cvt.u32.u64 %0, t; }" : "=r"(a) : "l"(p));
    return a;
}
__device__ __forceinline__ uint32_t f2tf32(float x) {
    uint32_t r;
    asm("cvt.rna.tf32.f32 %0, %1;" : "=r"(r) : "f"(x));
    return r;
}
__device__ __forceinline__ void mma_tf32(float* d, const uint32_t* a, const uint32_t* b) {
    asm volatile(
        "mma.sync.aligned.m16n8k8.row.col.f32.tf32.tf32.f32 "
        "{%0,%1,%2,%3}, {%4,%5,%6,%7}, {%8,%9}, {%0,%1,%2,%3};\n"
        : "+f"(d[0]), "+f"(d[1]), "+f"(d[2]), "+f"(d[3])
        : "r"(a[0]), "r"(a[1]), "r"(a[2]), "r"(a[3]), "r"(b[0]), "r"(b[1]));
}
#define CP_ASYNC16(dst, src) \
    asm volatile("cp.async.cg.shared.global [%0], [%1], 16;" :: "r"(dst), "l"(src))
#define CP_COMMIT()  asm volatile("cp.async.commit_group;" ::: "memory")
#define CP_WAIT0()   asm volatile("cp.async.wait_group 0;" ::: "memory")

// ---------------- prepack W -> tf32 smem-image tiles ----------------
// 144 images x 1024 16B-units; 2 units per thread for MLP
__global__ __launch_bounds__(256) void prepack_W(const float* __restrict__ W) {
    const int gt = blockIdx.x * 256 + threadIdx.x;   // 73728 threads
    #pragma unroll
    for (int h = 0; h < 2; h++) {
        const int u     = gt + h * 73728;            // 0..147455
        const int image = u >> 10;
        const int rem   = u & 1023;
        const int row   = rem >> 3;                  // 0..127
        const int c4    = rem & 7;

        const int seg  = image / (2 * KT);
        const int rem2 = image % (2 * KT);
        const int cblk = rem2 / KT;
        const int kt   = rem2 % KT;

        const int cls = cblk * 128 + row;
        float4 v = make_float4(0.f, 0.f, 0.f, 0.f);
        if (cls < C_)
            v = *(const float4*)(W + (size_t)cls * WLD + seg * D_ + kt * BK + c4 * 4);

        uint4 o = make_uint4(f2tf32(v.x), f2tf32(v.y), f2tf32(v.z), f2tf32(v.w));
        *(uint4*)(g_Wimg32 + (size_t)image * (128 * P32) + row * P32 + c4 * 4) = o;
    }
}

// ---------------- fused triple GEMM (tf32 mma, single product) ----------------
__global__ __launch_bounds__(256, 2) void tfgemm_fused(
    const float* __restrict__ A0,
    const float* __restrict__ A1,
    const float* __restrict__ A2,
    const float* __restrict__ bias,
    float* __restrict__ C0,
    float* __restrict__ C1,
    float* __restrict__ C2)
{
    // segment select
    int bx = blockIdx.x;
    const float* A;
    float* C;
    int M, seg;
    if (bx < NBLK_MAIN)                { A = A0; C = C0; M = B_ * L_; seg = 0; }
    else if (bx < NBLK_MAIN + NBLK_PE) { A = A1; C = C1; M = PE_ROWS; seg = 1; bx -= NBLK_MAIN; }
    else                               { A = A2; C = C2; M = CE_ROWS; seg = 2; bx -= NBLK_MAIN + NBLK_PE; }
    const int m0   = bx * BM;
    const int cblk = blockIdx.y;
    const int c0   = cblk * BN;

    extern __shared__ __align__(16) char smem[];
    uint32_t* SW32 = (uint32_t*)smem;
    const uint32_t sb = smem_u32(smem);

    const int tid  = threadIdx.x;
    const int lane = tid & 31;
    const int wid  = tid >> 5;
    const int warp_m = wid & 1;    // 2 M-warps (64 rows)
    const int warp_n = wid >> 1;   // 4 N-warps (32 cols)
    const int g   = lane >> 2;     // 0..7
    const int tig = lane & 3;      // 0..3

    // A staging geometry
    const int st_row = tid >> 3;   // +32 per i
    const int st_c4  = tid & 7;

    const uint32_t* wimg = g_Wimg32 + (size_t)((seg * 2 + cblk) * KT) * (128 * P32);

    float acc[4][4][4];
    #pragma unroll
    for (int mt = 0; mt < 4; mt++)
        #pragma unroll
        for (int nt = 0; nt < 4; nt++)
            #pragma unroll
            for (int r = 0; r < 4; r++) acc[mt][nt][r] = 0.f;

    auto stageB = [&](int kt, int bwoff) {
        const uint32_t dstb = sb + (uint32_t)bwoff * 4;
        const char* src = (const char*)(wimg + (size_t)kt * (128 * P32));
        #pragma unroll
        for (int i = 0; i < 5; i++) {
            const int idx = tid + i * 256;
            if (idx < 1152)
                CP_ASYNC16(dstb + (uint32_t)idx * 16, src + (size_t)idx * 16);
        }
        CP_COMMIT();
    };
    auto loadA = [&](int kt, float4* av) {
        #pragma unroll
        for (int i = 0; i < 4; i++) {
            const int row = st_row + i * 32;
            av[i] = make_float4(0.f, 0.f, 0.f, 0.f);
            if (m0 + row < M)
                av[i] = *(const float4*)(A + (size_t)(m0 + row) * D_ + kt * BK + st_c4 * 4);
        }
    };
    auto storeA = [&](const float4* av, int awoff) {
        #pragma unroll
        for (int i = 0; i < 4; i++) {
            const int row = st_row + i * 32;
            uint4 o = make_uint4(f2tf32(av[i].x), f2tf32(av[i].y),
                                 f2tf32(av[i].z), f2tf32(av[i].w));
            *(uint4*)(SW32 + awoff + row * P32 + st_c4 * 4) = o;
        }
    };

    // prologue
    float4 av[4];
    stageB(0, BW0);
    loadA(0, av);
    storeA(av, AW0);
    CP_WAIT0();
    __syncthreads();

    #pragma unroll 1
    for (int kt = 0; kt < KT; kt++) {
        const int b = kt & 1;
        const bool more = (kt + 1) < KT;
        if (more) {                    // issue next-tile loads BEFORE compute
            stageB(kt + 1, b ? BW0 : BW1);
            loadA(kt + 1, av);
        }

        const uint32_t* As = SW32 + (b ? AW1 : AW0);
        const uint32_t* Bs = SW32 + (b ? BW1 : BW0);

        #pragma unroll
        for (int ks = 0; ks < 4; ks++) {
            const int k0 = ks * 8 + tig;
            uint32_t bf[4][2];
            #pragma unroll
            for (int nt = 0; nt < 4; nt++) {
                const int naddr = (warp_n * 32 + nt * 8 + g) * P32 + k0;
                bf[nt][0] = Bs[naddr];
                bf[nt][1] = Bs[naddr + 4];
            }
            #pragma unroll
            for (int mt = 0; mt < 4; mt++) {
                const int maddr = (warp_m * 64 + mt * 16 + g) * P32 + k0;
                uint32_t a[4];
                a[0] = As[maddr];
                a[1] = As[maddr + 8 * P32];
                a[2] = As[maddr + 4];
                a[3] = As[maddr + 8 * P32 + 4];
                #pragma unroll
                for (int nt = 0; nt < 4; nt++)
                    mma_tf32(acc[mt][nt], a, bf[nt]);
            }
        }

        if (more) {
            storeA(av, b ? AW0 : AW1);   // convert+store AFTER compute (latency hidden)
            CP_WAIT0();
            __syncthreads();
        }
    }

    // ---- store (bias folded into CEW segment) ----
    #pragma unroll
    for (int mt = 0; mt < 4; mt++) {
        const int m_g = m0 + warp_m * 64 + mt * 16 + g;
        #pragma unroll
        for (int nt = 0; nt < 4; nt++) {
            const int n_g = c0 + warp_n * 32 + nt * 8 + 2 * tig;
            if (n_g < C_) {
                float b0 = 0.f, b1 = 0.f;
                if (seg == 2) { b0 = bias[n_g]; b1 = bias[n_g + 1]; }
                if (m_g < M)
                    *(float2*)(C + (size_t)m_g * C_ + n_g) =
                        make_float2(acc[mt][nt][0] + b0, acc[mt][nt][1] + b1);
                if (m_g + 8 < M)
                    *(float2*)(C + (size_t)(m_g + 8) * C_ + n_g) =
                        make_float2(acc[mt][nt][2] + b0, acc[mt][nt][3] + b1);
            }
        }
    }
}

// ---------------- gather + add epilogue (2 rows per thread for MLP) ----------------
__global__ __launch_bounds__(256) void epilogue_kernel(
    const int* __restrict__ head_indexes,
    const int* __restrict__ frame,
    const int* __restrict__ pos,
    float* __restrict__ out)
{
    const int t = threadIdx.x;
    const int lane = t & 63;
    if (lane >= C_ / 4) return;
    const int base = (blockIdx.x << 3) + (t >> 6);   // rows base..base+7, this thread: base, base+4

    #pragma unroll
    for (int h = 0; h < 2; h++) {
        const int r = base + h * 4;
        const int b = r >> 8;
        const int l = r & 255;

        const int hi  = __ldg(&head_indexes[r]);
        const int p   = __ldg(&pos[b]);
        const int rel = l - p + 256;
        const int fk  = (l == p) ? __ldg(&frame[b]) : 0;

        const float4 s = ((const float4*)(g_SW  + ((size_t)b * L_ + hi) * C_))[lane];
        const float4 q = ((const float4*)(g_PEW + (size_t)rel * C_))[lane];
        const float4 f = ((const float4*)(g_CEW + (size_t)fk  * C_))[lane];

        float4 o;
        o.x = s.x + q.x + f.x;
        o.y = s.y + q.y + f.y;
        o.z = s.z + q.z + f.z;
        o.w = s.w + q.w + f.w;
        ((float4*)(out + (size_t)r * C_))[lane] = o;
    }
}

extern "C" void kernel_launch(void* const* d_in, const int* in_sizes, int n_in,
                              void* d_out, int out_size)
{
    const float* seq   = (const float*)d_in[0];
    const float* pe    = (const float*)d_in[1];
    const float* ce    = (const float*)d_in[2];
    const float* W     = (const float*)d_in[3];
    const float* bias  = (const float*)d_in[4];
    const int*   hidx  = (const int*)  d_in[5];
    const int*   frame = (const int*)  d_in[6];
    const int*   pos   = (const int*)  d_in[7];
    float* out = (float*)d_out;

    float *dSW, *dPEW, *dCEW;
    cudaGetSymbolAddress((void**)&dSW,  g_SW);
    cudaGetSymbolAddress((void**)&dPEW, g_PEW);
    cudaGetSymbolAddress((void**)&dCEW, g_CEW);

    static int init_done = 0;
    if (!init_done) {
        cudaFuncSetAttribute(tfgemm_fused,
                             cudaFuncAttributeMaxDynamicSharedMemorySize, SMEM_TOT);
        init_done = 1;
    }

    // 1) prepack W -> tf32 smem tile images
    prepack_W<<<288, 256>>>(W);

    // 2) fused triple GEMM
    dim3 gG(NBLK_MAIN + NBLK_PE + NBLK_CE, 2);   // (135, 2)
    tfgemm_fused<<<gG, 256, SMEM_TOT>>>(seq, pe, ce, bias, dSW, dPEW, dCEW);

    // 3) gather + add epilogue
    epilogue_kernel<<<(B_ * L_) / 8, 256>>>(hidx, frame, pos, out);
}